// round 13
// baseline (speedup 1.0000x reference)
#include <cuda_runtime.h>
#include <math.h>

#define TMAX 2048
// element layout (floats): mu[0..127], logw at 128, pad to 136, Sigma 128x128
#define ELT 16520
#define MU_OFF 0
#define W_OFF 128
#define SIG_OFF 136
#define STR 196         // stride of fused 64x193 workspace [S(64) | W(128) | d(1)] + pad
#define D_COL 192
#define STRZ 132        // stride of z-only workspace [S(64) | Wq(64) | d(1)] + pad
#define D_COLZ 128
#define NT 256
#define LOG2PI 1.8378770664093453f

// ---------------- device scratch (static; no allocations) ----------------
__device__ float gTvar[128 * 128];
__device__ float gBufA[(size_t)TMAX * ELT];
__device__ float gBufB[(size_t)(TMAX / 2) * ELT];
__device__ float gEG[ELT];   // bare transition joint
__device__ float gEP[ELT];   // prior N(0,I) (degenerate in x)
__device__ float gEI[ELT];   // eInit = compose(gEP, gEG)
__device__ float gFin[ELT];  // final element (z-side only valid)

// ---------------- Tvar = tcho^T @ tcho (one block) ----------------
__global__ void __launch_bounds__(NT) prek_kernel(const float* __restrict__ tcho) {
    extern __shared__ float s[];   // 128*128
    int tid = threadIdx.x;
    for (int i = tid; i < 128 * 128; i += NT) s[i] = tcho[i];
    __syncthreads();
    int i0 = (tid >> 4) * 8, j0 = (tid & 15) * 8;
    float acc[8][8];
#pragma unroll
    for (int q = 0; q < 8; q++)
#pragma unroll
        for (int w = 0; w < 8; w++) acc[q][w] = 0.f;
    for (int k = 0; k < 128; ++k) {
        const float* row = s + (k << 7);
        float a[8], b[8];
#pragma unroll
        for (int q = 0; q < 8; q++) a[q] = row[i0 + q];
#pragma unroll
        for (int w = 0; w < 8; w++) b[w] = row[j0 + w];
#pragma unroll
        for (int q = 0; q < 8; q++)
#pragma unroll
            for (int w = 0; w < 8; w++) acc[q][w] += a[q] * b[w];
    }
#pragma unroll
    for (int q = 0; q < 8; q++)
#pragma unroll
        for (int w = 0; w < 8; w++) gTvar[(i0 + q) * 128 + j0 + w] = acc[q][w];
}

// ---------------- boundary elements ----------------
__global__ void __launch_bounds__(NT) einit_kernel(const float* __restrict__ tmu) {
    int tid = threadIdx.x;
    for (int i = tid; i < 128 * 128; i += NT) {
        gEG[SIG_OFF + i] = gTvar[i];
        int r = i >> 7, c = i & 127;
        gEP[SIG_OFF + i] = (r == c && r >= 64) ? 1.f : 0.f;
    }
    if (tid < 128) { gEG[MU_OFF + tid] = tmu[tid]; gEP[MU_OFF + tid] = 0.f; }
    if (tid == 0) { gEG[W_OFF] = 0.f; gEP[W_OFF] = 0.f; }
}

// ---------------- fast blocked LU on fused [S | RHS] (64 x NCOLS), no staging ----------------
// Right-looking, panel=16. Warp 0 factors each 64x16 panel in registers (warp-sync),
// builds L11^{-1}; TRSM (GEMM1) computes U12 into registers from UNMODIFIED A12
// (panel factor only writes cols c0..c0+15), then writes back after a barrier.
// On exit: diag = pivots, RHS columns hold L^{-1} * RHS.
template<int STRIDE, int NCOLS>
__device__ __forceinline__ void factor_fast(float* sA, float* sL11inv, int tid, int bs) {
    const int gTot = (NCOLS + 3) >> 2;
    int wid = tid >> 5, lane = tid & 31;
#pragma unroll 1
    for (int p = 0; p < 4; ++p) {
        int c0 = p << 4;
        int g0 = (c0 + 16) >> 2;
        int tw = gTot - g0;
        if (wid == 0) {
            // ---- panel factorization in registers (warp-sync) ----
            int nrp = 64 - c0;
            int r0 = c0 + lane, r1 = r0 + 32;
            bool h0 = lane < nrp, h1 = lane + 32 < nrp;
            float a0[16], a1[16];
#pragma unroll
            for (int k = 0; k < 16; ++k) {
                a0[k] = h0 ? sA[r0 * STRIDE + c0 + k] : 0.f;
                a1[k] = h1 ? sA[r1 * STRIDE + c0 + k] : 0.f;
            }
#pragma unroll
            for (int jj = 0; jj < 16; ++jj) {
                float bk[16];
#pragma unroll
                for (int k = 0; k < 16; ++k) bk[k] = __shfl_sync(~0u, a0[k], jj);
                float rp = __frcp_rn(bk[jj]);
                if (h0 && lane > jj) {
                    float m = a0[jj] * rp; a0[jj] = m;
#pragma unroll
                    for (int k = 0; k < 16; ++k) if (k > jj) a0[k] -= m * bk[k];
                }
                if (h1) {
                    float m = a1[jj] * rp; a1[jj] = m;
#pragma unroll
                    for (int k = 0; k < 16; ++k) if (k > jj) a1[k] -= m * bk[k];
                }
            }
#pragma unroll
            for (int k = 0; k < 16; ++k) {
                if (h0) sA[r0 * STRIDE + c0 + k] = a0[k];
                if (h1) sA[r1 * STRIDE + c0 + k] = a1[k];
            }
            __syncwarp();
            // ---- explicit L11^{-1} (unit-lower, multipliers in sA) ----
            if (lane < 16) {
                int c = lane;
                float x[16];
#pragma unroll
                for (int j = 0; j < 16; ++j) {
                    float s = 0.f;
#pragma unroll
                    for (int k = 0; k < 16; ++k)
                        if (k < j) s += sA[(c0 + j) * STRIDE + c0 + k] * x[k];
                    x[j] = (j == c) ? 1.f : ((j < c) ? 0.f : -s);
                }
#pragma unroll
                for (int j = 0; j < 16; ++j) sL11inv[j * 16 + c] = x[j];
            }
        }
        __syncthreads();
        // ---- GEMM1 (TRSM) into registers: U12 = L11inv @ A12(original) ----
        float4 acc[3];
#pragma unroll
        for (int it = 0; it < 3; ++it) {
            int m = tid + it * bs;
            if (m < 16 * tw) {
                int i = m / tw, gg = m - i * tw;
                float4 a = {0.f, 0.f, 0.f, 0.f};
#pragma unroll
                for (int k = 0; k < 16; ++k) {
                    float f = sL11inv[i * 16 + k];
                    const float4 b = *(const float4*)(sA + (c0 + k) * STRIDE + ((g0 + gg) << 2));
                    a.x += f * b.x; a.y += f * b.y; a.z += f * b.z; a.w += f * b.w;
                }
                acc[it] = a;
            }
        }
        __syncthreads();
#pragma unroll
        for (int it = 0; it < 3; ++it) {
            int m = tid + it * bs;
            if (m < 16 * tw) {
                int i = m / tw, gg = m - i * tw;
                *(float4*)(sA + (c0 + i) * STRIDE + ((g0 + gg) << 2)) = acc[it];
            }
        }
        __syncthreads();
        // ---- GEMM2: A22 -= L21 @ U12 (rank 16) ----
        int rs = c0 + 16, nr = 64 - rs;
        for (int m = tid; m < nr * tw; m += bs) {
            int q = m / tw, gg = m - q * tw;
            int r = rs + q;
            float4 a = *(const float4*)(sA + r * STRIDE + ((g0 + gg) << 2));
            float4 f0 = *(const float4*)(sA + r * STRIDE + c0);
            float4 f1 = *(const float4*)(sA + r * STRIDE + c0 + 4);
            float4 f2 = *(const float4*)(sA + r * STRIDE + c0 + 8);
            float4 f3 = *(const float4*)(sA + r * STRIDE + c0 + 12);
            float fs[16] = {f0.x, f0.y, f0.z, f0.w, f1.x, f1.y, f1.z, f1.w,
                            f2.x, f2.y, f2.z, f2.w, f3.x, f3.y, f3.z, f3.w};
#pragma unroll
            for (int k = 0; k < 16; ++k) {
                const float4 b = *(const float4*)(sA + (c0 + k) * STRIDE + ((g0 + gg) << 2));
                a.x -= fs[k] * b.x; a.y -= fs[k] * b.y; a.z -= fs[k] * b.z; a.w -= fs[k] * b.w;
            }
            *(float4*)(sA + r * STRIDE + ((g0 + gg) << 2)) = a;
        }
        __syncthreads();
    }
}

// ---------------- shared epilogue: precise inv, scaled RHS, score pieces ----------------
__device__ __forceinline__ void pivot_epilogue2(const float* sA, int stride, int dcol,
                                                float* sInv, float* sTv, float* sRed, int tid) {
    float val = 0.f;
    if (tid < 64) {
        float piv = sA[tid * stride + tid];
        float iv = 1.0f / piv;
        sInv[tid] = iv;
        float y = sA[tid * stride + dcol];
        sTv[tid] = y * iv;
        val = logf(piv) + y * y * iv;
    }
    for (int o = 16; o > 0; o >>= 1) val += __shfl_down_sync(~0u, val, o);
    if (tid == 0) sRed[0] = val;
    if (tid == 32) sRed[1] = val;
}

// ---------------- Schur GEMM core: acc[8][4] for W rows i0..i0+7, cols c..c+3 ----------------
__device__ __forceinline__ void schur_acc2(const float* sA, const float* sInv, int stride,
                                           int i0, int c, float acc[8][4]) {
#pragma unroll
    for (int q = 0; q < 8; q++)
#pragma unroll
        for (int w = 0; w < 4; w++) acc[q][w] = 0.f;
    for (int k = 0; k < 64; ++k) {
        const float* row = sA + k * stride + 64;
        float iv = sInv[k];
        float4 bv = *(const float4*)(row + c);
        float b[4] = {bv.x * iv, bv.y * iv, bv.z * iv, bv.w * iv};
        float4 a0 = *(const float4*)(row + i0);
        float4 a1 = *(const float4*)(row + i0 + 4);
        float a[8] = {a0.x, a0.y, a0.z, a0.w, a1.x, a1.y, a1.z, a1.w};
#pragma unroll
        for (int q = 0; q < 8; q++)
#pragma unroll
            for (int w = 0; w < 4; w++) acc[q][w] += a[q] * b[w];
    }
}

// ---------------- leaf: h_t = N(x; im_t, D_t) * N([x;z]; tmu, Tvar) ----------------
__global__ void __launch_bounds__(NT, 4) leaf_kernel(const int* __restrict__ sent,
                                                     const float* __restrict__ memb,
                                                     const float* __restrict__ cemb,
                                                     const float* __restrict__ tmu) {
    extern __shared__ float sm[];
    float* sA = sm;                     // 64 x STR
    float* sL11inv = sA + 64 * STR;     // 16 x 16
    float* sInv = sL11inv + 256;
    float* sTv = sInv + 64;
    float* sRed = sTv + 64;
    int t = blockIdx.x, tid = threadIdx.x;
    int wid = tid >> 5, lane = tid & 31;
    int tok = sent[t];
    for (int idx = tid; idx < 64 * 128; idx += NT) {
        int r = idx >> 7, c = idx & 127;
        float v = gTvar[r * 128 + c];
        sA[r * STR + 64 + c] = v;              // W = Tvar rows 0..63 (full 128 cols)
        if (c < 64) sA[r * STR + c] = v;       // S = Saa
    }
    __syncthreads();
    if (tid < 64) {
        float ch = cemb[tok * 64 + tid];
        sA[tid * STR + tid] += ch * ch;                           // S = Saa + D
        sA[tid * STR + D_COL] = memb[tok * 64 + tid] - tmu[tid];  // d = im - mu_a
        sA[tid * STR + 193] = 0.f; sA[tid * STR + 194] = 0.f; sA[tid * STR + 195] = 0.f;
    }
    __syncthreads();
    factor_fast<STR, 193>(sA, sL11inv, tid, NT);
    pivot_epilogue2(sA, STR, D_COL, sInv, sTv, sRed, tid);
    __syncthreads();
    float* eo = gBufA + (size_t)t * ELT;
    if (tid < 128) {      // mu' = tmu + W^T D^-1 y
        float a = 0.f;
        for (int k = 0; k < 64; ++k) a += sA[k * STR + 64 + tid] * sTv[k];
        eo[MU_OFF + tid] = tmu[tid] + a;
    }
    if (tid == 128) eo[W_OFF] = -0.5f * (64.f * LOG2PI + sRed[0] + sRed[1]);

    // Sigma' = Tvar - W^T D^-1 W  — full 128x128, warp-row-block, coalesced
    int c = lane << 2;
    for (int rb = wid; rb < 16; rb += 8) {
        int i0 = rb << 3;
        float acc[8][4];
        schur_acc2(sA, sInv, STR, i0, c, acc);
#pragma unroll
        for (int q = 0; q < 8; q++) {
            int r = i0 + q;
            float4 base = *(const float4*)(gTvar + r * 128 + c);
            float4 vv;
            vv.x = base.x - acc[q][0];
            vv.y = base.y - acc[q][1];
            vv.z = base.z - acc[q][2];
            vv.w = base.w - acc[q][3];
            *(float4*)(eo + SIG_OFF + r * 128 + c) = vv;
        }
    }
}

// ---------------- shared compose body ----------------
__device__ __forceinline__ void compose_body(const float* __restrict__ e1,
                                             const float* __restrict__ e2,
                                             float* __restrict__ eo,
                                             float* sm, int tid, int bs) {
    float* sA = sm;
    float* sL11inv = sA + 64 * STR;
    float* sInv = sL11inv + 256;
    float* sTv = sInv + 64;
    float* sRed = sTv + 64;
    int wid = tid >> 5, lane = tid & 31, nw = bs >> 5;
    const float* S1 = e1 + SIG_OFF;
    const float* S2 = e2 + SIG_OFF;
    for (int idx = tid; idx < 64 * 64; idx += bs) {
        int r = idx >> 6, c = idx & 63;
        sA[r * STR + c] = S1[(64 + r) * 128 + 64 + c] + S2[r * 128 + c];  // P_yy + Q_yy
        sA[r * STR + 64 + c] = S1[(64 + r) * 128 + c];                     // P_yx
        sA[r * STR + 128 + c] = S2[r * 128 + 64 + c];                      // Q_yz
    }
    if (tid < 64) {
        sA[tid * STR + D_COL] = e1[MU_OFF + 64 + tid] - e2[MU_OFF + tid];  // d
        sA[tid * STR + 193] = 0.f; sA[tid * STR + 194] = 0.f; sA[tid * STR + 195] = 0.f;
    }
    __syncthreads();
    factor_fast<STR, 193>(sA, sL11inv, tid, bs);
    pivot_epilogue2(sA, STR, D_COL, sInv, sTv, sRed, tid);
    __syncthreads();
    if (tid < 64) {        // mu'_x = m1_x - W_P^T D^-1 y
        float a = 0.f;
        for (int k = 0; k < 64; ++k) a += sA[k * STR + 64 + tid] * sTv[k];
        eo[MU_OFF + tid] = e1[MU_OFF + tid] - a;
    } else if (tid < 128) { // mu'_z = m2_z + W_Q^T D^-1 y
        int cc = tid - 64;
        float a = 0.f;
        for (int k = 0; k < 64; ++k) a += sA[k * STR + 128 + cc] * sTv[k];
        eo[MU_OFF + tid] = e2[MU_OFF + 64 + cc] + a;
    }
    if (tid == 128)
        eo[W_OFF] = e1[W_OFF] + e2[W_OFF] - 0.5f * (64.f * LOG2PI + sRed[0] + sRed[1]);

    // Sigma' full 128x128
    int c = lane << 2;
    for (int rb = wid; rb < 16; rb += nw) {
        int i0 = rb << 3;
        float acc[8][4];
        schur_acc2(sA, sInv, STR, i0, c, acc);
        bool cLow = (c < 64);
#pragma unroll
        for (int q = 0; q < 8; q++) {
            int r = i0 + q;
            float4 vv;
            if (r < 64 && cLow) {
                float4 base = *(const float4*)(S1 + r * 128 + c);
                vv.x = base.x - acc[q][0]; vv.y = base.y - acc[q][1];
                vv.z = base.z - acc[q][2]; vv.w = base.w - acc[q][3];
            } else if (r >= 64 && !cLow) {
                float4 base = *(const float4*)(S2 + r * 128 + c);
                vv.x = base.x - acc[q][0]; vv.y = base.y - acc[q][1];
                vv.z = base.z - acc[q][2]; vv.w = base.w - acc[q][3];
            } else {
                vv.x = acc[q][0]; vv.y = acc[q][1];
                vv.z = acc[q][2]; vv.w = acc[q][3];
            }
            *(float4*)(eo + SIG_OFF + r * 128 + c) = vv;
        }
    }
}

// wide levels: 256 threads, min 4 CTAs/SM (caps regs at 64)
__global__ void __launch_bounds__(NT, 4) compose_wide_kernel(const float* __restrict__ e1b,
                                                             const float* __restrict__ e2b,
                                                             float* __restrict__ eob) {
    extern __shared__ float sm[];
    const float* e1 = e1b + (size_t)blockIdx.x * (size_t)(2 * ELT);
    const float* e2 = e1 + ELT;
    float* eo = eob + (size_t)blockIdx.x * (size_t)ELT;
    compose_body(e1, e2, eo, sm, threadIdx.x, NT);
}

// tail levels: 512 threads (occupancy irrelevant, latency matters)
__global__ void __launch_bounds__(512) compose_tail_kernel(const float* __restrict__ e1b,
                                                           const float* __restrict__ e2b,
                                                           float* __restrict__ eob,
                                                           long sIn, long sOut) {
    extern __shared__ float sm[];
    const float* e1 = e1b + (size_t)blockIdx.x * (size_t)sIn;
    const float* e2 = e2b + (size_t)blockIdx.x * (size_t)sIn;
    float* eo = eob + (size_t)blockIdx.x * (size_t)sOut;
    compose_body(e1, e2, eo, sm, threadIdx.x, blockDim.x);
}

// ---------------- z-only final compose: only logw, mu_z, Sigma_zz of eI (.) root ----------------
__global__ void __launch_bounds__(512) compose_z_kernel(const float* __restrict__ e1,
                                                        const float* __restrict__ e2,
                                                        float* __restrict__ eo) {
    extern __shared__ float sm[];
    float* sA = sm;                      // 64 x STRZ : [S(64) | Wq(64) | d | pad]
    float* sL11inv = sA + 64 * STRZ;
    float* sInv = sL11inv + 256;
    float* sTv = sInv + 64;
    float* sRed = sTv + 64;
    int tid = threadIdx.x, bs = blockDim.x;
    int wid = tid >> 5, lane = tid & 31, nw = bs >> 5;
    const float* S1 = e1 + SIG_OFF;
    const float* S2 = e2 + SIG_OFF;
    for (int idx = tid; idx < 64 * 64; idx += bs) {
        int r = idx >> 6, c = idx & 63;
        sA[r * STRZ + c] = S1[(64 + r) * 128 + 64 + c] + S2[r * 128 + c];  // P_yy + Q_yy
        sA[r * STRZ + 64 + c] = S2[r * 128 + 64 + c];                       // Q_yz
    }
    if (tid < 64) {
        sA[tid * STRZ + D_COLZ] = e1[MU_OFF + 64 + tid] - e2[MU_OFF + tid];
        sA[tid * STRZ + 129] = 0.f; sA[tid * STRZ + 130] = 0.f; sA[tid * STRZ + 131] = 0.f;
    }
    __syncthreads();
    factor_fast<STRZ, 129>(sA, sL11inv, tid, bs);
    pivot_epilogue2(sA, STRZ, D_COLZ, sInv, sTv, sRed, tid);
    __syncthreads();
    if (tid < 64) {        // mu'_z = m2_z + W_Q^T D^-1 y
        float a = 0.f;
        for (int k = 0; k < 64; ++k) a += sA[k * STRZ + 64 + tid] * sTv[k];
        eo[MU_OFF + 64 + tid] = e2[MU_OFF + 64 + tid] + a;
    }
    if (tid == 64)
        eo[W_OFF] = e1[W_OFF] + e2[W_OFF] - 0.5f * (64.f * LOG2PI + sRed[0] + sRed[1]);
    // Sigma'_zz = S2_zz - Wq^T D^-1 Wq  (64x64)
    int c = (lane & 15) << 2;
    if (lane < 16) {
        for (int rb = wid; rb < 8; rb += nw) {
            int i0 = rb << 3;
            float acc[8][4];
            schur_acc2(sA, sInv, STRZ, i0, c, acc);
#pragma unroll
            for (int q = 0; q < 8; q++) {
                int r = i0 + q;
                float4 base = *(const float4*)(S2 + (64 + r) * 128 + 64 + c);
                float4 vv;
                vv.x = base.x - acc[q][0]; vv.y = base.y - acc[q][1];
                vv.z = base.z - acc[q][2]; vv.w = base.w - acc[q][3];
                *(float4*)(eo + SIG_OFF + (64 + r) * 128 + 64 + c) = vv;
            }
        }
    }
}

// ---------------- decode: 50 independent scores via the same fast factor ----------------
#define DSTR 68
__global__ void __launch_bounds__(NT) decode_kernel(const float* __restrict__ omu,
                                                    const float* __restrict__ ocho,
                                                    float* __restrict__ out, int nlab) {
    extern __shared__ float sm[];
    float* sA = sm;                    // 64 x DSTR, cols: S(64) | z(1) | pad
    float* sL11inv = sA + 64 * DSTR;
    float* sRed = sL11inv + 256;
    int l = blockIdx.x, tid = threadIdx.x;
    if (l >= nlab) return;
    for (int idx = tid; idx < 64 * 64; idx += NT) {
        int r = idx >> 6, c = idx & 63;
        sA[r * DSTR + c] = gFin[SIG_OFF + (64 + r) * 128 + 64 + c];
    }
    __syncthreads();
    if (tid < 64) {
        float oc = ocho[l * 64 + tid];
        sA[tid * DSTR + tid] += oc * oc;
        sA[tid * DSTR + 64] = gFin[MU_OFF + 64 + tid] - omu[l * 64 + tid];
        sA[tid * DSTR + 65] = 0.f; sA[tid * DSTR + 66] = 0.f; sA[tid * DSTR + 67] = 0.f;
    }
    __syncthreads();
    factor_fast<DSTR, 65>(sA, sL11inv, tid, NT);
    float val = 0.f;
    if (tid < 64) {
        float piv = sA[tid * DSTR + tid];
        float y = sA[tid * DSTR + 64];
        val = logf(piv) + y * y / piv;
    }
    for (int o = 16; o > 0; o >>= 1) val += __shfl_down_sync(~0u, val, o);
    if (tid == 0) sRed[0] = val;
    if (tid == 32) sRed[1] = val;
    __syncthreads();
    if (tid == 0) out[l] = gFin[W_OFF] - 0.5f * (64.f * LOG2PI + sRed[0] + sRed[1]);
}

// ---------------- launch ----------------
static const int CSM  = (64 * STR + 256 + 64 + 64 + 8) * 4;
static const int CSMZ = (64 * STRZ + 256 + 64 + 64 + 8) * 4;
static const int DSM  = (64 * DSTR + 256 + 8) * 4;

extern "C" void kernel_launch(void* const* d_in, const int* in_sizes, int n_in,
                              void* d_out, int out_size) {
    const int*   sent = (const int*)d_in[0];
    const float* memb = (const float*)d_in[2];
    const float* cemb = (const float*)d_in[3];
    const float* tmu  = (const float*)d_in[4];
    const float* tcho = (const float*)d_in[5];
    const float* omu  = (const float*)d_in[6];
    const float* ocho = (const float*)d_in[7];
    float* out = (float*)d_out;

    int n = in_sizes[0];
    if (n > TMAX) n = TMAX;
    if (n < 1) n = 1;
    int nlab = out_size;
    if (nlab <= 0) nlab = in_sizes[6] / 64;

    cudaFuncSetAttribute(prek_kernel, cudaFuncAttributeMaxDynamicSharedMemorySize, 128 * 128 * 4);
    cudaFuncSetAttribute(leaf_kernel, cudaFuncAttributeMaxDynamicSharedMemorySize, CSM);
    cudaFuncSetAttribute(compose_wide_kernel, cudaFuncAttributeMaxDynamicSharedMemorySize, CSM);
    cudaFuncSetAttribute(compose_tail_kernel, cudaFuncAttributeMaxDynamicSharedMemorySize, CSM);
    cudaFuncSetAttribute(compose_z_kernel, cudaFuncAttributeMaxDynamicSharedMemorySize, CSMZ);
    cudaFuncSetAttribute(decode_kernel, cudaFuncAttributeMaxDynamicSharedMemorySize, DSM);

    float *bufA, *bufB, *eP, *eG, *eI, *fin;
    cudaGetSymbolAddress((void**)&bufA, gBufA);
    cudaGetSymbolAddress((void**)&bufB, gBufB);
    cudaGetSymbolAddress((void**)&eP, gEP);
    cudaGetSymbolAddress((void**)&eG, gEG);
    cudaGetSymbolAddress((void**)&eI, gEI);
    cudaGetSymbolAddress((void**)&fin, gFin);

    prek_kernel<<<1, NT, 128 * 128 * 4>>>(tcho);
    einit_kernel<<<1, NT>>>(tmu);
    compose_tail_kernel<<<1, 512, CSM>>>(eP, eG, eI, 0, 0);    // eInit = prior (.) joint
    leaf_kernel<<<n, NT, CSM>>>(sent, memb, cemb, tmu);

    float* src = bufA;
    float* dst = bufB;
    int m = n;
    while (m > 1) {
        int nc = m >> 1;
        if (nc > 148)
            compose_wide_kernel<<<nc, NT, CSM>>>(src, src + ELT, dst);
        else
            compose_tail_kernel<<<nc, 512, CSM>>>(src, src + ELT, dst,
                                                  (long)(2 * ELT), (long)ELT);
        if (m & 1)
            cudaMemcpyAsync(dst + (size_t)nc * ELT, src + (size_t)(m - 1) * ELT,
                            (size_t)ELT * sizeof(float), cudaMemcpyDeviceToDevice);
        m = (m + 1) >> 1;
        float* tp = src; src = dst; dst = tp;
    }
    compose_z_kernel<<<1, 512, CSMZ>>>(eI, src, fin);
    decode_kernel<<<nlab, NT, DSM>>>(omu, ocho, out, nlab);
}

// round 14
// speedup vs baseline: 1.0758x; 1.0758x over previous
#include <cuda_runtime.h>
#include <math.h>

#define TMAX 2048
// element layout (floats): mu[0..127], logw at 128, pad to 136, Sigma 128x128
#define ELT 16520
#define MU_OFF 0
#define W_OFF 128
#define SIG_OFF 136
#define STR 196         // stride of fused 64x193 workspace [S(64) | W(128) | d(1)] + pad
#define D_COL 192
#define STRZ 132        // stride of z-only workspace [S(64) | Wq(64) | d(1)] + pad
#define D_COLZ 128
#define NT 256
#define LOG2PI 1.8378770664093453f

// ---------------- device scratch (static; no allocations) ----------------
__device__ float gTvar[128 * 128];
__device__ float gBufA[(size_t)TMAX * ELT];
__device__ float gBufB[(size_t)(TMAX / 2) * ELT];
__device__ float gEG[ELT];   // bare transition joint
__device__ float gEP[ELT];   // prior N(0,I) (degenerate in x)
__device__ float gEI[ELT];   // eInit = compose(gEP, gEG)
__device__ float gFin[ELT];  // final element (z-side only valid)

// ---------------- Tvar = tcho^T @ tcho (one block) ----------------
__global__ void __launch_bounds__(NT) prek_kernel(const float* __restrict__ tcho) {
    extern __shared__ float s[];   // 128*128
    int tid = threadIdx.x;
    for (int i = tid; i < 128 * 128; i += NT) s[i] = tcho[i];
    __syncthreads();
    int i0 = (tid >> 4) * 8, j0 = (tid & 15) * 8;
    float acc[8][8];
#pragma unroll
    for (int q = 0; q < 8; q++)
#pragma unroll
        for (int w = 0; w < 8; w++) acc[q][w] = 0.f;
    for (int k = 0; k < 128; ++k) {
        const float* row = s + (k << 7);
        float a[8], b[8];
#pragma unroll
        for (int q = 0; q < 8; q++) a[q] = row[i0 + q];
#pragma unroll
        for (int w = 0; w < 8; w++) b[w] = row[j0 + w];
#pragma unroll
        for (int q = 0; q < 8; q++)
#pragma unroll
            for (int w = 0; w < 8; w++) acc[q][w] += a[q] * b[w];
    }
#pragma unroll
    for (int q = 0; q < 8; q++)
#pragma unroll
        for (int w = 0; w < 8; w++) gTvar[(i0 + q) * 128 + j0 + w] = acc[q][w];
}

// ---------------- boundary elements ----------------
__global__ void __launch_bounds__(NT) einit_kernel(const float* __restrict__ tmu) {
    int tid = threadIdx.x;
    for (int i = tid; i < 128 * 128; i += NT) {
        gEG[SIG_OFF + i] = gTvar[i];
        int r = i >> 7, c = i & 127;
        gEP[SIG_OFF + i] = (r == c && r >= 64) ? 1.f : 0.f;
    }
    if (tid < 128) { gEG[MU_OFF + tid] = tmu[tid]; gEP[MU_OFF + tid] = 0.f; }
    if (tid == 0) { gEG[W_OFF] = 0.f; gEP[W_OFF] = 0.f; }
}

// ---------------- fast blocked LU on fused [S | RHS] (64 x NCOLS) ----------------
// Right-looking, panel=16. Warp 0 factors each 64x16 panel in registers (warp-sync),
// builds L11^{-1}; TRSM (GEMM1) computes U12 into registers from UNMODIFIED A12
// (4 rows per thread, one op/thread), writes back after a barrier; GEMM2 does the
// rank-16 trailing update with 4 rows per thread (b reused across rows).
// On exit: diag = pivots, RHS columns hold L^{-1} * RHS.
template<int STRIDE, int NCOLS>
__device__ __forceinline__ void factor_fast(float* sA, float* sL11inv, int tid, int bs) {
    const int gTot = (NCOLS + 3) >> 2;
    int wid = tid >> 5, lane = tid & 31;
#pragma unroll 1
    for (int p = 0; p < 4; ++p) {
        int c0 = p << 4;
        int g0 = (c0 + 16) >> 2;
        int tw = gTot - g0;
        if (wid == 0) {
            // ---- panel factorization in registers (warp-sync) ----
            int nrp = 64 - c0;
            int r0 = c0 + lane, r1 = r0 + 32;
            bool h0 = lane < nrp, h1 = lane + 32 < nrp;
            float a0[16], a1[16];
#pragma unroll
            for (int k = 0; k < 16; ++k) {
                a0[k] = h0 ? sA[r0 * STRIDE + c0 + k] : 0.f;
                a1[k] = h1 ? sA[r1 * STRIDE + c0 + k] : 0.f;
            }
#pragma unroll
            for (int jj = 0; jj < 16; ++jj) {
                float bk[16];
#pragma unroll
                for (int k = 0; k < 16; ++k) bk[k] = __shfl_sync(~0u, a0[k], jj);
                float rp = __frcp_rn(bk[jj]);
                if (h0 && lane > jj) {
                    float m = a0[jj] * rp; a0[jj] = m;
#pragma unroll
                    for (int k = 0; k < 16; ++k) if (k > jj) a0[k] -= m * bk[k];
                }
                if (h1) {
                    float m = a1[jj] * rp; a1[jj] = m;
#pragma unroll
                    for (int k = 0; k < 16; ++k) if (k > jj) a1[k] -= m * bk[k];
                }
            }
#pragma unroll
            for (int k = 0; k < 16; ++k) {
                if (h0) sA[r0 * STRIDE + c0 + k] = a0[k];
                if (h1) sA[r1 * STRIDE + c0 + k] = a1[k];
            }
            __syncwarp();
            // ---- explicit L11^{-1} (unit-lower, multipliers in sA) ----
            if (lane < 16) {
                int c = lane;
                float x[16];
#pragma unroll
                for (int j = 0; j < 16; ++j) {
                    float s = 0.f;
#pragma unroll
                    for (int k = 0; k < 16; ++k)
                        if (k < j) s += sA[(c0 + j) * STRIDE + c0 + k] * x[k];
                    x[j] = (j == c) ? 1.f : ((j < c) ? 0.f : -s);
                }
#pragma unroll
                for (int j = 0; j < 16; ++j) sL11inv[j * 16 + c] = x[j];
            }
        }
        __syncthreads();
        // ---- GEMM1 (TRSM): U12 = L11inv @ A12(original), 4 rows/thread, 1 op/thread ----
        float4 acc1[4];
        int m1 = tid;
        bool act1 = (m1 < 4 * tw);
        int i4 = 0, col1 = 0;
        if (act1) {
            i4 = m1 / tw;
            col1 = (g0 + (m1 - i4 * tw)) << 2;
#pragma unroll
            for (int q = 0; q < 4; ++q) acc1[q] = make_float4(0.f, 0.f, 0.f, 0.f);
#pragma unroll 1
            for (int k = 0; k < 16; ++k) {
                const float4 b = *(const float4*)(sA + (c0 + k) * STRIDE + col1);
#pragma unroll
                for (int q = 0; q < 4; ++q) {
                    float f = sL11inv[(i4 * 4 + q) * 16 + k];
                    acc1[q].x += f * b.x; acc1[q].y += f * b.y;
                    acc1[q].z += f * b.z; acc1[q].w += f * b.w;
                }
            }
        }
        __syncthreads();
        if (act1) {
#pragma unroll
            for (int q = 0; q < 4; ++q)
                *(float4*)(sA + (c0 + i4 * 4 + q) * STRIDE + col1) = acc1[q];
        }
        __syncthreads();
        // ---- GEMM2: A22 -= L21 @ U12 (rank 16), 4 rows/thread ----
        int rs = c0 + 16, nr = 64 - rs;
        int nq = nr >> 2;
        for (int m = tid; m < nq * tw; m += bs) {
            int q4 = m / tw, gg = m - q4 * tw;
            int r = rs + q4 * 4;
            int col = (g0 + gg) << 2;
            float4 a0 = *(const float4*)(sA + (r + 0) * STRIDE + col);
            float4 a1 = *(const float4*)(sA + (r + 1) * STRIDE + col);
            float4 a2 = *(const float4*)(sA + (r + 2) * STRIDE + col);
            float4 a3 = *(const float4*)(sA + (r + 3) * STRIDE + col);
#pragma unroll 1
            for (int k = 0; k < 16; ++k) {
                const float4 b = *(const float4*)(sA + (c0 + k) * STRIDE + col);
                float f0 = sA[(r + 0) * STRIDE + c0 + k];
                float f1 = sA[(r + 1) * STRIDE + c0 + k];
                float f2 = sA[(r + 2) * STRIDE + c0 + k];
                float f3 = sA[(r + 3) * STRIDE + c0 + k];
                a0.x -= f0 * b.x; a0.y -= f0 * b.y; a0.z -= f0 * b.z; a0.w -= f0 * b.w;
                a1.x -= f1 * b.x; a1.y -= f1 * b.y; a1.z -= f1 * b.z; a1.w -= f1 * b.w;
                a2.x -= f2 * b.x; a2.y -= f2 * b.y; a2.z -= f2 * b.z; a2.w -= f2 * b.w;
                a3.x -= f3 * b.x; a3.y -= f3 * b.y; a3.z -= f3 * b.z; a3.w -= f3 * b.w;
            }
            *(float4*)(sA + (r + 0) * STRIDE + col) = a0;
            *(float4*)(sA + (r + 1) * STRIDE + col) = a1;
            *(float4*)(sA + (r + 2) * STRIDE + col) = a2;
            *(float4*)(sA + (r + 3) * STRIDE + col) = a3;
        }
        __syncthreads();
    }
}

// ---------------- shared epilogue: precise inv, scaled RHS, score pieces ----------------
__device__ __forceinline__ void pivot_epilogue2(const float* sA, int stride, int dcol,
                                                float* sInv, float* sTv, float* sRed, int tid) {
    float val = 0.f;
    if (tid < 64) {
        float piv = sA[tid * stride + tid];
        float iv = 1.0f / piv;
        sInv[tid] = iv;
        float y = sA[tid * stride + dcol];
        sTv[tid] = y * iv;
        val = logf(piv) + y * y * iv;
    }
    for (int o = 16; o > 0; o >>= 1) val += __shfl_down_sync(~0u, val, o);
    if (tid == 0) sRed[0] = val;
    if (tid == 32) sRed[1] = val;
}

// ---------------- Schur 32x32 warp tile: thread = 4 rows x 8 cols ----------------
// Output(i,j) over W columns: acc[q][w] = sum_k W[k][wb+i0+rg*4+q]*inv[k]*W[k][wb+j0+cg*8+w]
// rg = lane&7, cg = lane>>3. a-loads 4-way broadcast, b-loads 8-way broadcast.
__device__ __forceinline__ void schur_tile32(const float* sA, const float* sInv, int stride,
                                             int wb, int i0, int j0, int lane,
                                             float acc[4][8]) {
    int ra = wb + i0 + (lane & 7) * 4;
    int cb = wb + j0 + (lane >> 3) * 8;
#pragma unroll
    for (int q = 0; q < 4; q++)
#pragma unroll
        for (int w = 0; w < 8; w++) acc[q][w] = 0.f;
#pragma unroll 1
    for (int k = 0; k < 64; ++k) {
        const float* row = sA + k * stride;
        float iv = sInv[k];
        float4 av = *(const float4*)(row + ra);
        float4 b0 = *(const float4*)(row + cb);
        float4 b1 = *(const float4*)(row + cb + 4);
        float a[4] = {av.x * iv, av.y * iv, av.z * iv, av.w * iv};
        float b[8] = {b0.x, b0.y, b0.z, b0.w, b1.x, b1.y, b1.z, b1.w};
#pragma unroll
        for (int q = 0; q < 4; q++)
#pragma unroll
            for (int w = 0; w < 8; w++) acc[q][w] += a[q] * b[w];
    }
}

// ---------------- leaf: h_t = N(x; im_t, D_t) * N([x;z]; tmu, Tvar) ----------------
__global__ void __launch_bounds__(NT, 3) leaf_kernel(const int* __restrict__ sent,
                                                     const float* __restrict__ memb,
                                                     const float* __restrict__ cemb,
                                                     const float* __restrict__ tmu) {
    extern __shared__ float sm[];
    float* sA = sm;                     // 64 x STR
    float* sL11inv = sA + 64 * STR;     // 16 x 16
    float* sInv = sL11inv + 256;
    float* sTv = sInv + 64;
    float* sRed = sTv + 64;
    int t = blockIdx.x, tid = threadIdx.x;
    int wid = tid >> 5, lane = tid & 31;
    int tok = sent[t];
    for (int idx = tid; idx < 64 * 128; idx += NT) {
        int r = idx >> 7, c = idx & 127;
        float v = gTvar[r * 128 + c];
        sA[r * STR + 64 + c] = v;              // W = Tvar rows 0..63 (full 128 cols)
        if (c < 64) sA[r * STR + c] = v;       // S = Saa
    }
    __syncthreads();
    if (tid < 64) {
        float ch = cemb[tok * 64 + tid];
        sA[tid * STR + tid] += ch * ch;                           // S = Saa + D
        sA[tid * STR + D_COL] = memb[tok * 64 + tid] - tmu[tid];  // d = im - mu_a
        sA[tid * STR + 193] = 0.f; sA[tid * STR + 194] = 0.f; sA[tid * STR + 195] = 0.f;
    }
    __syncthreads();
    factor_fast<STR, 193>(sA, sL11inv, tid, NT);
    pivot_epilogue2(sA, STR, D_COL, sInv, sTv, sRed, tid);
    __syncthreads();
    float* eo = gBufA + (size_t)t * ELT;
    if (tid < 128) {      // mu' = tmu + W^T D^-1 y
        float a = 0.f;
        for (int k = 0; k < 64; ++k) a += sA[k * STR + 64 + tid] * sTv[k];
        eo[MU_OFF + tid] = tmu[tid] + a;
    }
    if (tid == 128) eo[W_OFF] = -0.5f * (64.f * LOG2PI + sRed[0] + sRed[1]);

    // Sigma' = Tvar - W^T D^-1 W : 16 tiles of 32x32
    for (int tt = wid; tt < 16; tt += 8) {
        int i0 = (tt >> 2) * 32, j0 = (tt & 3) * 32;
        float acc[4][8];
        schur_tile32(sA, sInv, STR, 64, i0, j0, lane, acc);
        int rbase = i0 + (lane & 7) * 4;
        int cb = j0 + (lane >> 3) * 8;
#pragma unroll
        for (int q = 0; q < 4; ++q) {
            int r = rbase + q;
            float4 b0 = *(const float4*)(gTvar + r * 128 + cb);
            float4 b1 = *(const float4*)(gTvar + r * 128 + cb + 4);
            float4 v0, v1;
            v0.x = b0.x - acc[q][0]; v0.y = b0.y - acc[q][1];
            v0.z = b0.z - acc[q][2]; v0.w = b0.w - acc[q][3];
            v1.x = b1.x - acc[q][4]; v1.y = b1.y - acc[q][5];
            v1.z = b1.z - acc[q][6]; v1.w = b1.w - acc[q][7];
            *(float4*)(eo + SIG_OFF + r * 128 + cb) = v0;
            *(float4*)(eo + SIG_OFF + r * 128 + cb + 4) = v1;
        }
    }
}

// ---------------- shared compose body ----------------
__device__ __forceinline__ void compose_body(const float* __restrict__ e1,
                                             const float* __restrict__ e2,
                                             float* __restrict__ eo,
                                             float* sm, int tid, int bs) {
    float* sA = sm;
    float* sL11inv = sA + 64 * STR;
    float* sInv = sL11inv + 256;
    float* sTv = sInv + 64;
    float* sRed = sTv + 64;
    int wid = tid >> 5, lane = tid & 31, nw = bs >> 5;
    const float* S1 = e1 + SIG_OFF;
    const float* S2 = e2 + SIG_OFF;
    for (int idx = tid; idx < 64 * 64; idx += bs) {
        int r = idx >> 6, c = idx & 63;
        sA[r * STR + c] = S1[(64 + r) * 128 + 64 + c] + S2[r * 128 + c];  // P_yy + Q_yy
        sA[r * STR + 64 + c] = S1[(64 + r) * 128 + c];                     // P_yx
        sA[r * STR + 128 + c] = S2[r * 128 + 64 + c];                      // Q_yz
    }
    if (tid < 64) {
        sA[tid * STR + D_COL] = e1[MU_OFF + 64 + tid] - e2[MU_OFF + tid];  // d
        sA[tid * STR + 193] = 0.f; sA[tid * STR + 194] = 0.f; sA[tid * STR + 195] = 0.f;
    }
    __syncthreads();
    factor_fast<STR, 193>(sA, sL11inv, tid, bs);
    pivot_epilogue2(sA, STR, D_COL, sInv, sTv, sRed, tid);
    __syncthreads();
    if (tid < 64) {        // mu'_x = m1_x - W_P^T D^-1 y
        float a = 0.f;
        for (int k = 0; k < 64; ++k) a += sA[k * STR + 64 + tid] * sTv[k];
        eo[MU_OFF + tid] = e1[MU_OFF + tid] - a;
    } else if (tid < 128) { // mu'_z = m2_z + W_Q^T D^-1 y
        int cc = tid - 64;
        float a = 0.f;
        for (int k = 0; k < 64; ++k) a += sA[k * STR + 128 + cc] * sTv[k];
        eo[MU_OFF + tid] = e2[MU_OFF + 64 + cc] + a;
    }
    if (tid == 128)
        eo[W_OFF] = e1[W_OFF] + e2[W_OFF] - 0.5f * (64.f * LOG2PI + sRed[0] + sRed[1]);

    // Sigma' full 128x128: 16 tiles of 32x32 (each tile lies in one quadrant)
    for (int tt = wid; tt < 16; tt += nw) {
        int i0 = (tt >> 2) * 32, j0 = (tt & 3) * 32;
        float acc[4][8];
        schur_tile32(sA, sInv, STR, 64, i0, j0, lane, acc);
        int rbase = i0 + (lane & 7) * 4;
        int cb = j0 + (lane >> 3) * 8;
        bool rLow = (i0 < 64), cLow = (j0 < 64);
#pragma unroll
        for (int q = 0; q < 4; ++q) {
            int r = rbase + q;
            float4 v0, v1;
            if (rLow && cLow) {
                float4 b0 = *(const float4*)(S1 + r * 128 + cb);
                float4 b1 = *(const float4*)(S1 + r * 128 + cb + 4);
                v0.x = b0.x - acc[q][0]; v0.y = b0.y - acc[q][1];
                v0.z = b0.z - acc[q][2]; v0.w = b0.w - acc[q][3];
                v1.x = b1.x - acc[q][4]; v1.y = b1.y - acc[q][5];
                v1.z = b1.z - acc[q][6]; v1.w = b1.w - acc[q][7];
            } else if (!rLow && !cLow) {
                float4 b0 = *(const float4*)(S2 + r * 128 + cb);
                float4 b1 = *(const float4*)(S2 + r * 128 + cb + 4);
                v0.x = b0.x - acc[q][0]; v0.y = b0.y - acc[q][1];
                v0.z = b0.z - acc[q][2]; v0.w = b0.w - acc[q][3];
                v1.x = b1.x - acc[q][4]; v1.y = b1.y - acc[q][5];
                v1.z = b1.z - acc[q][6]; v1.w = b1.w - acc[q][7];
            } else {
                v0.x = acc[q][0]; v0.y = acc[q][1]; v0.z = acc[q][2]; v0.w = acc[q][3];
                v1.x = acc[q][4]; v1.y = acc[q][5]; v1.z = acc[q][6]; v1.w = acc[q][7];
            }
            *(float4*)(eo + SIG_OFF + r * 128 + cb) = v0;
            *(float4*)(eo + SIG_OFF + r * 128 + cb + 4) = v1;
        }
    }
}

// wide levels: 256 threads, min 3 CTAs/SM
__global__ void __launch_bounds__(NT, 3) compose_wide_kernel(const float* __restrict__ e1b,
                                                             const float* __restrict__ e2b,
                                                             float* __restrict__ eob) {
    extern __shared__ float sm[];
    const float* e1 = e1b + (size_t)blockIdx.x * (size_t)(2 * ELT);
    const float* e2 = e1 + ELT;
    float* eo = eob + (size_t)blockIdx.x * (size_t)ELT;
    compose_body(e1, e2, eo, sm, threadIdx.x, NT);
}

// tail levels: 512 threads (occupancy irrelevant, latency matters)
__global__ void __launch_bounds__(512) compose_tail_kernel(const float* __restrict__ e1b,
                                                           const float* __restrict__ e2b,
                                                           float* __restrict__ eob,
                                                           long sIn, long sOut) {
    extern __shared__ float sm[];
    const float* e1 = e1b + (size_t)blockIdx.x * (size_t)sIn;
    const float* e2 = e2b + (size_t)blockIdx.x * (size_t)sIn;
    float* eo = eob + (size_t)blockIdx.x * (size_t)sOut;
    compose_body(e1, e2, eo, sm, threadIdx.x, blockDim.x);
}

// ---------------- z-only final compose: only logw, mu_z, Sigma_zz of eI (.) root ----------------
__global__ void __launch_bounds__(512) compose_z_kernel(const float* __restrict__ e1,
                                                        const float* __restrict__ e2,
                                                        float* __restrict__ eo) {
    extern __shared__ float sm[];
    float* sA = sm;                      // 64 x STRZ : [S(64) | Wq(64) | d | pad]
    float* sL11inv = sA + 64 * STRZ;
    float* sInv = sL11inv + 256;
    float* sTv = sInv + 64;
    float* sRed = sTv + 64;
    int tid = threadIdx.x, bs = blockDim.x;
    int wid = tid >> 5, lane = tid & 31, nw = bs >> 5;
    const float* S1 = e1 + SIG_OFF;
    const float* S2 = e2 + SIG_OFF;
    for (int idx = tid; idx < 64 * 64; idx += bs) {
        int r = idx >> 6, c = idx & 63;
        sA[r * STRZ + c] = S1[(64 + r) * 128 + 64 + c] + S2[r * 128 + c];  // P_yy + Q_yy
        sA[r * STRZ + 64 + c] = S2[r * 128 + 64 + c];                       // Q_yz
    }
    if (tid < 64) {
        sA[tid * STRZ + D_COLZ] = e1[MU_OFF + 64 + tid] - e2[MU_OFF + tid];
        sA[tid * STRZ + 129] = 0.f; sA[tid * STRZ + 130] = 0.f; sA[tid * STRZ + 131] = 0.f;
    }
    __syncthreads();
    factor_fast<STRZ, 129>(sA, sL11inv, tid, bs);
    pivot_epilogue2(sA, STRZ, D_COLZ, sInv, sTv, sRed, tid);
    __syncthreads();
    if (tid < 64) {        // mu'_z = m2_z + W_Q^T D^-1 y
        float a = 0.f;
        for (int k = 0; k < 64; ++k) a += sA[k * STRZ + 64 + tid] * sTv[k];
        eo[MU_OFF + 64 + tid] = e2[MU_OFF + 64 + tid] + a;
    }
    if (tid == 64)
        eo[W_OFF] = e1[W_OFF] + e2[W_OFF] - 0.5f * (64.f * LOG2PI + sRed[0] + sRed[1]);
    // Sigma'_zz = S2_zz - Wq^T D^-1 Wq  (64x64): 4 tiles of 32x32
    for (int tt = wid; tt < 4; tt += nw) {
        int i0 = (tt >> 1) * 32, j0 = (tt & 1) * 32;
        float acc[4][8];
        schur_tile32(sA, sInv, STRZ, 64, i0, j0, lane, acc);
        int rbase = i0 + (lane & 7) * 4;
        int cb = j0 + (lane >> 3) * 8;
#pragma unroll
        for (int q = 0; q < 4; ++q) {
            int r = rbase + q;
            float4 b0 = *(const float4*)(S2 + (64 + r) * 128 + 64 + cb);
            float4 b1 = *(const float4*)(S2 + (64 + r) * 128 + 64 + cb + 4);
            float4 v0, v1;
            v0.x = b0.x - acc[q][0]; v0.y = b0.y - acc[q][1];
            v0.z = b0.z - acc[q][2]; v0.w = b0.w - acc[q][3];
            v1.x = b1.x - acc[q][4]; v1.y = b1.y - acc[q][5];
            v1.z = b1.z - acc[q][6]; v1.w = b1.w - acc[q][7];
            *(float4*)(eo + SIG_OFF + (64 + r) * 128 + 64 + cb) = v0;
            *(float4*)(eo + SIG_OFF + (64 + r) * 128 + 64 + cb + 4) = v1;
        }
    }
}

// ---------------- decode: 50 independent scores via the same fast factor ----------------
#define DSTR 68
__global__ void __launch_bounds__(NT) decode_kernel(const float* __restrict__ omu,
                                                    const float* __restrict__ ocho,
                                                    float* __restrict__ out, int nlab) {
    extern __shared__ float sm[];
    float* sA = sm;                    // 64 x DSTR, cols: S(64) | z(1) | pad
    float* sL11inv = sA + 64 * DSTR;
    float* sRed = sL11inv + 256;
    int l = blockIdx.x, tid = threadIdx.x;
    if (l >= nlab) return;
    for (int idx = tid; idx < 64 * 64; idx += NT) {
        int r = idx >> 6, c = idx & 63;
        sA[r * DSTR + c] = gFin[SIG_OFF + (64 + r) * 128 + 64 + c];
    }
    __syncthreads();
    if (tid < 64) {
        float oc = ocho[l * 64 + tid];
        sA[tid * DSTR + tid] += oc * oc;
        sA[tid * DSTR + 64] = gFin[MU_OFF + 64 + tid] - omu[l * 64 + tid];
        sA[tid * DSTR + 65] = 0.f; sA[tid * DSTR + 66] = 0.f; sA[tid * DSTR + 67] = 0.f;
    }
    __syncthreads();
    factor_fast<DSTR, 65>(sA, sL11inv, tid, NT);
    float val = 0.f;
    if (tid < 64) {
        float piv = sA[tid * DSTR + tid];
        float y = sA[tid * DSTR + 64];
        val = logf(piv) + y * y / piv;
    }
    for (int o = 16; o > 0; o >>= 1) val += __shfl_down_sync(~0u, val, o);
    if (tid == 0) sRed[0] = val;
    if (tid == 32) sRed[1] = val;
    __syncthreads();
    if (tid == 0) out[l] = gFin[W_OFF] - 0.5f * (64.f * LOG2PI + sRed[0] + sRed[1]);
}

// ---------------- launch ----------------
static const int CSM  = (64 * STR + 256 + 64 + 64 + 8) * 4;
static const int CSMZ = (64 * STRZ + 256 + 64 + 64 + 8) * 4;
static const int DSM  = (64 * DSTR + 256 + 8) * 4;

extern "C" void kernel_launch(void* const* d_in, const int* in_sizes, int n_in,
                              void* d_out, int out_size) {
    const int*   sent = (const int*)d_in[0];
    const float* memb = (const float*)d_in[2];
    const float* cemb = (const float*)d_in[3];
    const float* tmu  = (const float*)d_in[4];
    const float* tcho = (const float*)d_in[5];
    const float* omu  = (const float*)d_in[6];
    const float* ocho = (const float*)d_in[7];
    float* out = (float*)d_out;

    int n = in_sizes[0];
    if (n > TMAX) n = TMAX;
    if (n < 1) n = 1;
    int nlab = out_size;
    if (nlab <= 0) nlab = in_sizes[6] / 64;

    cudaFuncSetAttribute(prek_kernel, cudaFuncAttributeMaxDynamicSharedMemorySize, 128 * 128 * 4);
    cudaFuncSetAttribute(leaf_kernel, cudaFuncAttributeMaxDynamicSharedMemorySize, CSM);
    cudaFuncSetAttribute(compose_wide_kernel, cudaFuncAttributeMaxDynamicSharedMemorySize, CSM);
    cudaFuncSetAttribute(compose_tail_kernel, cudaFuncAttributeMaxDynamicSharedMemorySize, CSM);
    cudaFuncSetAttribute(compose_z_kernel, cudaFuncAttributeMaxDynamicSharedMemorySize, CSMZ);
    cudaFuncSetAttribute(decode_kernel, cudaFuncAttributeMaxDynamicSharedMemorySize, DSM);

    float *bufA, *bufB, *eP, *eG, *eI, *fin;
    cudaGetSymbolAddress((void**)&bufA, gBufA);
    cudaGetSymbolAddress((void**)&bufB, gBufB);
    cudaGetSymbolAddress((void**)&eP, gEP);
    cudaGetSymbolAddress((void**)&eG, gEG);
    cudaGetSymbolAddress((void**)&eI, gEI);
    cudaGetSymbolAddress((void**)&fin, gFin);

    prek_kernel<<<1, NT, 128 * 128 * 4>>>(tcho);
    einit_kernel<<<1, NT>>>(tmu);
    compose_tail_kernel<<<1, 512, CSM>>>(eP, eG, eI, 0, 0);    // eInit = prior (.) joint
    leaf_kernel<<<n, NT, CSM>>>(sent, memb, cemb, tmu);

    float* src = bufA;
    float* dst = bufB;
    int m = n;
    while (m > 1) {
        int nc = m >> 1;
        if (nc > 148)
            compose_wide_kernel<<<nc, NT, CSM>>>(src, src + ELT, dst);
        else
            compose_tail_kernel<<<nc, 512, CSM>>>(src, src + ELT, dst,
                                                  (long)(2 * ELT), (long)ELT);
        if (m & 1)
            cudaMemcpyAsync(dst + (size_t)nc * ELT, src + (size_t)(m - 1) * ELT,
                            (size_t)ELT * sizeof(float), cudaMemcpyDeviceToDevice);
        m = (m + 1) >> 1;
        float* tp = src; src = dst; dst = tp;
    }
    compose_z_kernel<<<1, 512, CSMZ>>>(eI, src, fin);
    decode_kernel<<<nlab, NT, DSM>>>(omu, ocho, out, nlab);
}